// round 15
// baseline (speedup 1.0000x reference)
#include <cuda_runtime.h>
#include <math.h>

#define NN 100000
#define EE 1600000
#define OUTD 64
#define IND 128
#define NBLK ((NN + 255) / 256)   // 391 scan blocks

// ---- scratch (static __device__ arrays; no allocation allowed) ----
static __device__ float g_Wh[(size_t)NN * OUTD];        // 25.6 MB
static __device__ float g_asrc[NN * 4];
static __device__ float g_adst[NN * 4];
static __device__ int   g_count[NN];
static __device__ unsigned g_stat[NBLK];                // scan aggregates (bit31 = ready)
static __device__ int   g_rowstart[NN];
static __device__ int   g_cursor[NN];
static __device__ int   g_csr_src[EE];                  // 6.4 MB
static __device__ float g_csr_ex[(size_t)EE * 4];       // 25.6 MB

__device__ __forceinline__ float dot4(float4 a, float4 b) {
    return a.x * b.x + a.y * b.y + a.z * b.z + a.w * b.w;
}

// ---- K1: GEMM Wh = x @ Wn^T. 4 nodes/thread, 4 adjacent cols/thread,
//      XOR-swizzled smem W. Also zeroes g_count/g_stat (runs first). ----
__global__ void __launch_bounds__(256) k_node(
    const float* __restrict__ x, const float* __restrict__ Wn,
    const float* __restrict__ att_s, const float* __restrict__ att_d) {
    __shared__ float4 Wt[64 * 32];   // 32 KB; unit u = col*32 + (f ^ ((col>>2)&7))
    int t = threadIdx.x;
    int tx = t & 15, ty = t >> 4;

    int zi = blockIdx.x * 256 + t;
    if (zi < NN) g_count[zi] = 0;
    else if (zi < NN + NBLK) g_stat[zi - NN] = 0u;

    const float4* W4 = (const float4*)Wn;
#pragma unroll
    for (int i = 0; i < 8; i++) {
        int fidx = t + i * 256;          // 0..2047
        int col = fidx >> 5;
        int f = fidx & 31;
        Wt[col * 32 + (f ^ ((col >> 2) & 7))] = __ldg(W4 + fidx);
    }

    int nbase = blockIdx.x * 64 + ty * 4;
    const float4* xp[4];
    int node[4];
#pragma unroll
    for (int i = 0; i < 4; i++) {
        node[i] = nbase + i;
        int nc = (node[i] < NN) ? node[i] : (NN - 1);
        xp[i] = (const float4*)x + (size_t)nc * 32;
    }

    float4 acc[4];
#pragma unroll
    for (int i = 0; i < 4; i++) acc[i] = make_float4(0.f, 0.f, 0.f, 0.f);

    __syncthreads();

    int sw = tx & 7;
#pragma unroll 4
    for (int kk = 0; kk < 32; kk++) {
        float4 xv[4];
#pragma unroll
        for (int i = 0; i < 4; i++) xv[i] = __ldg(xp[i] + kk);
        float4 w0 = Wt[(4 * tx + 0) * 32 + (kk ^ sw)];
        float4 w1 = Wt[(4 * tx + 1) * 32 + (kk ^ sw)];
        float4 w2 = Wt[(4 * tx + 2) * 32 + (kk ^ sw)];
        float4 w3 = Wt[(4 * tx + 3) * 32 + (kk ^ sw)];
#pragma unroll
        for (int i = 0; i < 4; i++) {
            acc[i].x += dot4(xv[i], w0);
            acc[i].y += dot4(xv[i], w1);
            acc[i].z += dot4(xv[i], w2);
            acc[i].w += dot4(xv[i], w3);
        }
    }

    float4 as4 = __ldg((const float4*)att_s + tx);
    float4 ad4 = __ldg((const float4*)att_d + tx);
    int h = tx >> 2;
#pragma unroll
    for (int i = 0; i < 4; i++) {
        float ps = dot4(acc[i], as4);
        float pd = dot4(acc[i], ad4);
        ps += __shfl_xor_sync(0xffffffffu, ps, 1);
        pd += __shfl_xor_sync(0xffffffffu, pd, 1);
        ps += __shfl_xor_sync(0xffffffffu, ps, 2);
        pd += __shfl_xor_sync(0xffffffffu, pd, 2);
        if ((tx & 3) == 0 && node[i] < NN) {
            g_asrc[node[i] * 4 + h] = ps;
            g_adst[node[i] * 4 + h] = pd;
        }
    }

#pragma unroll
    for (int i = 0; i < 4; i++) {
        if (node[i] < NN)
            *(float4*)(g_Wh + (size_t)node[i] * OUTD + 4 * tx) = acc[i];
    }
}

// ---- K2: degree histogram (no return use -> REDG fast path) ----
__global__ void __launch_bounds__(256) k_count(const int* __restrict__ ei) {
    int i = blockIdx.x * 256 + threadIdx.x;
    if (i < EE) atomicAdd(&g_count[__ldg(ei + EE + i)], 1);
}

// ---- K3: single-pass exclusive scan (block scan + aggregate lookback) ----
__global__ void __launch_bounds__(256) k_scan() {
    __shared__ int sh[256];
    __shared__ int prefix_sh;
    int b = blockIdx.x, t = threadIdx.x;
    int i = b * 256 + t;
    int c = (i < NN) ? g_count[i] : 0;
    sh[t] = c;
    __syncthreads();
#pragma unroll
    for (int o = 1; o < 256; o <<= 1) {
        int add = (t >= o) ? sh[t - o] : 0;
        __syncthreads();
        sh[t] += add;
        __syncthreads();
    }
    int incl = sh[t];
    if (t == 0) {
        unsigned total = (unsigned)sh[255];
        atomicExch(&g_stat[b], 0x80000000u | total);
    }
    if (t < 32) {
        int sum = 0;
        for (int idx = t; idx < b; idx += 32) {
            unsigned v;
            do { v = *(volatile unsigned*)&g_stat[idx]; } while (!(v & 0x80000000u));
            sum += (int)(v & 0x7fffffffu);
        }
#pragma unroll
        for (int o = 16; o >= 1; o >>= 1) sum += __shfl_xor_sync(0xffffffffu, sum, o);
        if (t == 0) prefix_sh = sum;
    }
    __syncthreads();
    if (i < NN) {
        int start = prefix_sh + incl - c;
        g_rowstart[i] = start;
        g_cursor[i] = start;
    }
}

// ---- K4: fused logits + exp + CSR bucket-scatter (no max shift:
//      alpha is shift-invariant up to the 1e-9 epsilon, ~1e-7 relative) ----
__global__ void __launch_bounds__(256) k_edge_fused(
    const int* __restrict__ ei, const float* __restrict__ ea,
    const float* __restrict__ We) {
    __shared__ float we[64];
    int t = threadIdx.x;
    if (t < 64) we[t] = We[t];
    __syncthreads();
    int i = blockIdx.x * 256 + t;
    if (i >= EE) return;
    int s = ei[i];
    int d = ei[EE + i];
    float eav[16];
    const float4* er = (const float4*)(ea + (size_t)i * 16);
#pragma unroll
    for (int j = 0; j < 4; j++) ((float4*)eav)[j] = __ldg(er + j);
    float4 as = *(const float4*)(g_asrc + (size_t)s * 4);
    float4 ad = *(const float4*)(g_adst + (size_t)d * 4);
    float base[4] = {as.x + ad.x, as.y + ad.y, as.z + ad.z, as.w + ad.w};
    float4 ex;
    float* exp_ = (float*)&ex;
#pragma unroll
    for (int h = 0; h < 4; h++) {
        float dot = 0.f;
        const float* w = we + h * 16;
#pragma unroll
        for (int k = 0; k < 16; k++) dot += eav[k] * w[k];
        float v = base[h] + dot;
        v = (v > 0.f) ? v : 0.2f * v;      // leaky_relu
        exp_[h] = __expf(v);                // no max shift
    }
    int pos = atomicAdd(&g_cursor[d], 1);
    g_csr_src[pos] = s;
    *(float4*)(g_csr_ex + (size_t)pos * 4) = ex;
}

// ---- K5: HALF-WARP-per-node aggregate. 16 nodes/block (NN = 6250*16).
//      Lane lx of each half owns cols 4lx..4lx+3; per edge the half does
//      one 256B coalesced Wh row gather. Halves loop to max(cnt0,cnt1). ----
__global__ void __launch_bounds__(256) k_agg(float* __restrict__ out,
                                             const float* __restrict__ bias) {
    __shared__ int   sh_src[16][16];
    __shared__ float sh_ex[16][64];
    int t = threadIdx.x;
    int hid = t >> 4;            // half-warp id in block (0..15)
    int lx = t & 15;
    int h = lx >> 2;
    int n = blockIdx.x * 16 + hid;       // NN = 6250*16 exactly, no guard
    int cnt = __ldg(g_count + n);
    int start = __ldg(g_rowstart + n);
    int maxcnt = max(cnt, __shfl_xor_sync(0xffffffffu, cnt, 16));
    float4 acc = make_float4(0.f, 0.f, 0.f, 0.f);
    float dp0 = 0.f, dp1 = 0.f, dp2 = 0.f, dp3 = 0.f;

    for (int j0 = 0; j0 < maxcnt; j0 += 16) {
        int m = min(16, cnt - j0);       // may be <= 0 for this half
        if (lx < m) {
            int idx = start + j0 + lx;
            int s = __ldg(g_csr_src + idx);
            float4 ex = *(const float4*)(g_csr_ex + (size_t)idx * 4);
            sh_src[hid][lx] = s;
            *(float4*)&sh_ex[hid][lx * 4] = ex;
            dp0 += ex.x; dp1 += ex.y; dp2 += ex.z; dp3 += ex.w;
        }
        __syncwarp();
        int j = 0;
        for (; j + 4 <= m; j += 4) {     // 4 independent gathers in flight
            int s0 = sh_src[hid][j + 0], s1 = sh_src[hid][j + 1];
            int s2 = sh_src[hid][j + 2], s3 = sh_src[hid][j + 3];
            float a0 = sh_ex[hid][(j + 0) * 4 + h];
            float a1 = sh_ex[hid][(j + 1) * 4 + h];
            float a2 = sh_ex[hid][(j + 2) * 4 + h];
            float a3 = sh_ex[hid][(j + 3) * 4 + h];
            float4 w0 = *(const float4*)(g_Wh + (size_t)s0 * OUTD + 4 * lx);
            float4 w1 = *(const float4*)(g_Wh + (size_t)s1 * OUTD + 4 * lx);
            float4 w2 = *(const float4*)(g_Wh + (size_t)s2 * OUTD + 4 * lx);
            float4 w3 = *(const float4*)(g_Wh + (size_t)s3 * OUTD + 4 * lx);
            acc.x += a0 * w0.x + a1 * w1.x + a2 * w2.x + a3 * w3.x;
            acc.y += a0 * w0.y + a1 * w1.y + a2 * w2.y + a3 * w3.y;
            acc.z += a0 * w0.z + a1 * w1.z + a2 * w2.z + a3 * w3.z;
            acc.w += a0 * w0.w + a1 * w1.w + a2 * w2.w + a3 * w3.w;
        }
        for (; j < m; j++) {
            int s = sh_src[hid][j];
            float a = sh_ex[hid][j * 4 + h];
            float4 wv = *(const float4*)(g_Wh + (size_t)s * OUTD + 4 * lx);
            acc.x += a * wv.x; acc.y += a * wv.y;
            acc.z += a * wv.z; acc.w += a * wv.w;
        }
        __syncwarp();
    }
    // den: reduce the 4 partials across the 16 lanes of this half
#pragma unroll
    for (int o = 8; o >= 1; o >>= 1) {
        dp0 += __shfl_xor_sync(0xffffffffu, dp0, o);
        dp1 += __shfl_xor_sync(0xffffffffu, dp1, o);
        dp2 += __shfl_xor_sync(0xffffffffu, dp2, o);
        dp3 += __shfl_xor_sync(0xffffffffu, dp3, o);
    }
    float den = (h == 0) ? dp0 : (h == 1) ? dp1 : (h == 2) ? dp2 : dp3;
    float inv = 1.f / (den + 1e-9f);
    float4 b4 = *(const float4*)(bias + 4 * lx);
    float4 r;
    r.x = acc.x * inv + b4.x;
    r.y = acc.y * inv + b4.y;
    r.z = acc.z * inv + b4.z;
    r.w = acc.w * inv + b4.w;
    r.x = (r.x > 0.f) ? r.x : expm1f(r.x);
    r.y = (r.y > 0.f) ? r.y : expm1f(r.y);
    r.z = (r.z > 0.f) ? r.z : expm1f(r.z);
    r.w = (r.w > 0.f) ? r.w : expm1f(r.w);
    *(float4*)(out + (size_t)n * OUTD + 4 * lx) = r;
}

extern "C" void kernel_launch(void* const* d_in, const int* in_sizes, int n_in,
                              void* d_out, int out_size) {
    const float* x     = (const float*)d_in[0];
    const int*   ei    = (const int*)d_in[1];
    const float* ea    = (const float*)d_in[2];
    const float* Wn    = (const float*)d_in[3];
    const float* We    = (const float*)d_in[4];
    const float* att_s = (const float*)d_in[5];
    const float* att_d = (const float*)d_in[6];
    const float* bias  = (const float*)d_in[7];
    float* out = (float*)d_out;

    int ebl = (EE + 255) / 256;
    k_node<<<(NN + 63) / 64, 256>>>(x, Wn, att_s, att_d); // 1 (also zeroes count/stat)
    k_count<<<ebl, 256>>>(ei);                            // 2
    k_scan<<<NBLK, 256>>>();                              // 3
    k_edge_fused<<<ebl, 256>>>(ei, ea, We);               // 4 <- ncu lands here
    k_agg<<<NN / 16, 256>>>(out, bias);                   // 5
}

// round 16
// speedup vs baseline: 1.3124x; 1.3124x over previous
#include <cuda_runtime.h>
#include <math.h>

#define NN 100000
#define EE 1600000
#define OUTD 64
#define IND 128
#define NBLK ((NN + 255) / 256)   // 391 scan blocks

// ---- scratch (static __device__ arrays; no allocation allowed) ----
static __device__ float g_Wh[(size_t)NN * OUTD];        // 25.6 MB
static __device__ float g_asrc[NN * 4];
static __device__ float g_adst[NN * 4];
static __device__ int   g_count[NN];
static __device__ unsigned g_stat[NBLK];                // scan aggregates (bit31 = ready)
static __device__ int   g_rowstart[NN];
static __device__ int   g_cursor[NN];
static __device__ int   g_csr_src[EE];                  // 6.4 MB
static __device__ float g_csr_ex[(size_t)EE * 4];       // 25.6 MB

__device__ __forceinline__ float dot4(float4 a, float4 b) {
    return a.x * b.x + a.y * b.y + a.z * b.z + a.w * b.w;
}

// ---- K1: GEMM Wh = x @ Wn^T. 4 nodes/thread, 4 adjacent cols/thread,
//      XOR-swizzled smem W. Also zeroes g_count/g_stat (runs first). ----
__global__ void __launch_bounds__(256) k_node(
    const float* __restrict__ x, const float* __restrict__ Wn,
    const float* __restrict__ att_s, const float* __restrict__ att_d) {
    __shared__ float4 Wt[64 * 32];   // 32 KB; unit u = col*32 + (f ^ ((col>>2)&7))
    int t = threadIdx.x;
    int tx = t & 15, ty = t >> 4;

    int zi = blockIdx.x * 256 + t;
    if (zi < NN) g_count[zi] = 0;
    else if (zi < NN + NBLK) g_stat[zi - NN] = 0u;

    const float4* W4 = (const float4*)Wn;
#pragma unroll
    for (int i = 0; i < 8; i++) {
        int fidx = t + i * 256;          // 0..2047
        int col = fidx >> 5;
        int f = fidx & 31;
        Wt[col * 32 + (f ^ ((col >> 2) & 7))] = __ldg(W4 + fidx);
    }

    int nbase = blockIdx.x * 64 + ty * 4;
    const float4* xp[4];
    int node[4];
#pragma unroll
    for (int i = 0; i < 4; i++) {
        node[i] = nbase + i;
        int nc = (node[i] < NN) ? node[i] : (NN - 1);
        xp[i] = (const float4*)x + (size_t)nc * 32;
    }

    float4 acc[4];
#pragma unroll
    for (int i = 0; i < 4; i++) acc[i] = make_float4(0.f, 0.f, 0.f, 0.f);

    __syncthreads();

    int sw = tx & 7;
#pragma unroll 4
    for (int kk = 0; kk < 32; kk++) {
        float4 xv[4];
#pragma unroll
        for (int i = 0; i < 4; i++) xv[i] = __ldg(xp[i] + kk);
        float4 w0 = Wt[(4 * tx + 0) * 32 + (kk ^ sw)];
        float4 w1 = Wt[(4 * tx + 1) * 32 + (kk ^ sw)];
        float4 w2 = Wt[(4 * tx + 2) * 32 + (kk ^ sw)];
        float4 w3 = Wt[(4 * tx + 3) * 32 + (kk ^ sw)];
#pragma unroll
        for (int i = 0; i < 4; i++) {
            acc[i].x += dot4(xv[i], w0);
            acc[i].y += dot4(xv[i], w1);
            acc[i].z += dot4(xv[i], w2);
            acc[i].w += dot4(xv[i], w3);
        }
    }

    float4 as4 = __ldg((const float4*)att_s + tx);
    float4 ad4 = __ldg((const float4*)att_d + tx);
    int h = tx >> 2;
#pragma unroll
    for (int i = 0; i < 4; i++) {
        float ps = dot4(acc[i], as4);
        float pd = dot4(acc[i], ad4);
        ps += __shfl_xor_sync(0xffffffffu, ps, 1);
        pd += __shfl_xor_sync(0xffffffffu, pd, 1);
        ps += __shfl_xor_sync(0xffffffffu, ps, 2);
        pd += __shfl_xor_sync(0xffffffffu, pd, 2);
        if ((tx & 3) == 0 && node[i] < NN) {
            g_asrc[node[i] * 4 + h] = ps;
            g_adst[node[i] * 4 + h] = pd;
        }
    }

#pragma unroll
    for (int i = 0; i < 4; i++) {
        if (node[i] < NN)
            *(float4*)(g_Wh + (size_t)node[i] * OUTD + 4 * tx) = acc[i];
    }
}

// ---- K2: degree histogram (no return use -> REDG fast path) ----
__global__ void __launch_bounds__(256) k_count(const int* __restrict__ ei) {
    int i = blockIdx.x * 256 + threadIdx.x;
    if (i < EE) atomicAdd(&g_count[__ldg(ei + EE + i)], 1);
}

// ---- K3: single-pass exclusive scan (block scan + aggregate lookback) ----
__global__ void __launch_bounds__(256) k_scan() {
    __shared__ int sh[256];
    __shared__ int prefix_sh;
    int b = blockIdx.x, t = threadIdx.x;
    int i = b * 256 + t;
    int c = (i < NN) ? g_count[i] : 0;
    sh[t] = c;
    __syncthreads();
#pragma unroll
    for (int o = 1; o < 256; o <<= 1) {
        int add = (t >= o) ? sh[t - o] : 0;
        __syncthreads();
        sh[t] += add;
        __syncthreads();
    }
    int incl = sh[t];
    if (t == 0) {
        unsigned total = (unsigned)sh[255];
        atomicExch(&g_stat[b], 0x80000000u | total);
    }
    if (t < 32) {
        int sum = 0;
        for (int idx = t; idx < b; idx += 32) {
            unsigned v;
            do { v = *(volatile unsigned*)&g_stat[idx]; } while (!(v & 0x80000000u));
            sum += (int)(v & 0x7fffffffu);
        }
#pragma unroll
        for (int o = 16; o >= 1; o >>= 1) sum += __shfl_xor_sync(0xffffffffu, sum, o);
        if (t == 0) prefix_sh = sum;
    }
    __syncthreads();
    if (i < NN) {
        int start = prefix_sh + incl - c;
        g_rowstart[i] = start;
        g_cursor[i] = start;
    }
}

// ---- K4: fused logits + exp + CSR bucket-scatter. We dot vectorized:
//      16 LDS.128 + 64 FFMA per thread (was 64 LDS.32 + 64 FFMA). ----
__global__ void __launch_bounds__(256) k_edge_fused(
    const int* __restrict__ ei, const float* __restrict__ ea,
    const float* __restrict__ We) {
    __shared__ float4 we4[16];       // we4[h*4+j] = We[h][4j..4j+3]
    int t = threadIdx.x;
    if (t < 16) we4[t] = __ldg((const float4*)We + t);
    __syncthreads();
    int i = blockIdx.x * 256 + t;
    if (i >= EE) return;
    int s = ei[i];
    int d = ei[EE + i];
    float4 eav[4];
    const float4* er = (const float4*)(ea + (size_t)i * 16);
#pragma unroll
    for (int j = 0; j < 4; j++) eav[j] = __ldg(er + j);
    float4 as = *(const float4*)(g_asrc + (size_t)s * 4);
    float4 ad = *(const float4*)(g_adst + (size_t)d * 4);
    float base[4] = {as.x + ad.x, as.y + ad.y, as.z + ad.z, as.w + ad.w};
    float4 ex;
    float* exp_ = (float*)&ex;
#pragma unroll
    for (int h = 0; h < 4; h++) {
        float dot = 0.f;
#pragma unroll
        for (int j = 0; j < 4; j++) dot += dot4(eav[j], we4[h * 4 + j]);
        float v = base[h] + dot;
        v = (v > 0.f) ? v : 0.2f * v;      // leaky_relu
        exp_[h] = __expf(v);                // no max shift (~1e-7 relative effect)
    }
    int pos = atomicAdd(&g_cursor[d], 1);
    g_csr_src[pos] = s;
    *(float4*)(g_csr_ex + (size_t)pos * 4) = ex;
}

// ---- K5: warp-per-node aggregate, LDS-staged, 4x-unrolled gathers ----
__global__ void __launch_bounds__(256) k_agg(float* __restrict__ out,
                                             const float* __restrict__ bias) {
    __shared__ int   sh_src[8][32];
    __shared__ float sh_ex[8][128];
    int w = threadIdx.x >> 5;
    int lane = threadIdx.x & 31;
    int n = blockIdx.x * 8 + w;
    if (n >= NN) return;
    int cnt = __ldg(g_count + n);
    int start = __ldg(g_rowstart + n);
    int h = lane >> 3;
    float acc0 = 0.f, acc1 = 0.f;
    float dp0 = 0.f, dp1 = 0.f, dp2 = 0.f, dp3 = 0.f;

    for (int j0 = 0; j0 < cnt; j0 += 32) {
        int m = min(32, cnt - j0);
        if (lane < m) {
            int idx = start + j0 + lane;
            int s = __ldg(g_csr_src + idx);
            float4 ex = *(const float4*)(g_csr_ex + (size_t)idx * 4);
            sh_src[w][lane] = s;
            *(float4*)&sh_ex[w][lane * 4] = ex;
            dp0 += ex.x; dp1 += ex.y; dp2 += ex.z; dp3 += ex.w;
        }
        __syncwarp();
        int j = 0;
        for (; j + 4 <= m; j += 4) {
            int s0 = sh_src[w][j + 0], s1 = sh_src[w][j + 1];
            int s2 = sh_src[w][j + 2], s3 = sh_src[w][j + 3];
            float a0 = sh_ex[w][(j + 0) * 4 + h];
            float a1 = sh_ex[w][(j + 1) * 4 + h];
            float a2 = sh_ex[w][(j + 2) * 4 + h];
            float a3 = sh_ex[w][(j + 3) * 4 + h];
            float2 w0 = *(const float2*)(g_Wh + (size_t)s0 * OUTD + lane * 2);
            float2 w1 = *(const float2*)(g_Wh + (size_t)s1 * OUTD + lane * 2);
            float2 w2 = *(const float2*)(g_Wh + (size_t)s2 * OUTD + lane * 2);
            float2 w3 = *(const float2*)(g_Wh + (size_t)s3 * OUTD + lane * 2);
            acc0 += a0 * w0.x + a1 * w1.x + a2 * w2.x + a3 * w3.x;
            acc1 += a0 * w0.y + a1 * w1.y + a2 * w2.y + a3 * w3.y;
        }
        for (; j < m; j++) {
            int s = sh_src[w][j];
            float a = sh_ex[w][j * 4 + h];
            float2 wv = *(const float2*)(g_Wh + (size_t)s * OUTD + lane * 2);
            acc0 += a * wv.x;
            acc1 += a * wv.y;
        }
        __syncwarp();
    }
#pragma unroll
    for (int o = 16; o >= 1; o >>= 1) {
        dp0 += __shfl_xor_sync(0xffffffffu, dp0, o);
        dp1 += __shfl_xor_sync(0xffffffffu, dp1, o);
        dp2 += __shfl_xor_sync(0xffffffffu, dp2, o);
        dp3 += __shfl_xor_sync(0xffffffffu, dp3, o);
    }
    float den = (h == 0) ? dp0 : (h == 1) ? dp1 : (h == 2) ? dp2 : dp3;
    float inv = 1.f / (den + 1e-9f);
    int c0 = lane * 2;
    float v0 = acc0 * inv + __ldg(bias + c0);
    float v1 = acc1 * inv + __ldg(bias + c0 + 1);
    float2 r;
    r.x = (v0 > 0.f) ? v0 : expm1f(v0);
    r.y = (v1 > 0.f) ? v1 : expm1f(v1);
    *(float2*)(out + (size_t)n * OUTD + c0) = r;
}

extern "C" void kernel_launch(void* const* d_in, const int* in_sizes, int n_in,
                              void* d_out, int out_size) {
    const float* x     = (const float*)d_in[0];
    const int*   ei    = (const int*)d_in[1];
    const float* ea    = (const float*)d_in[2];
    const float* Wn    = (const float*)d_in[3];
    const float* We    = (const float*)d_in[4];
    const float* att_s = (const float*)d_in[5];
    const float* att_d = (const float*)d_in[6];
    const float* bias  = (const float*)d_in[7];
    float* out = (float*)d_out;

    int ebl = (EE + 255) / 256;
    k_node<<<(NN + 63) / 64, 256>>>(x, Wn, att_s, att_d); // 1 (also zeroes count/stat)
    k_count<<<ebl, 256>>>(ei);                            // 2
    k_scan<<<NBLK, 256>>>();                              // 3
    k_edge_fused<<<ebl, 256>>>(ei, ea, We);               // 4 <- ncu lands here
    k_agg<<<(NN + 7) / 8, 256>>>(out, bias);              // 5
}

// round 17
// speedup vs baseline: 1.3394x; 1.0206x over previous
#include <cuda_runtime.h>
#include <math.h>

#define NN 100000
#define EE 1600000
#define OUTD 64
#define IND 128
#define NBLK ((NN + 255) / 256)   // 391 scan blocks

// ---- scratch (static __device__ arrays; no allocation allowed) ----
static __device__ float g_Wh[(size_t)NN * OUTD];        // 25.6 MB
static __device__ float g_asrc[NN * 4];
static __device__ float g_adst[NN * 4];
static __device__ int   g_count[NN];
static __device__ unsigned g_stat[NBLK];                // scan aggregates (bit31 = ready)
static __device__ int   g_rowstart[NN];
static __device__ int   g_cursor[NN];
static __device__ int   g_csr_src[EE];                  // 6.4 MB
static __device__ float g_csr_ex[(size_t)EE * 4];       // 25.6 MB

__device__ __forceinline__ float dot4(float4 a, float4 b) {
    return a.x * b.x + a.y * b.y + a.z * b.z + a.w * b.w;
}

// ---- K0 (side stream): zero counts + scan state ----
__global__ void __launch_bounds__(256) k_init() {
    int i = blockIdx.x * 256 + threadIdx.x;
    if (i < NN) g_count[i] = 0;
    else if (i < NN + NBLK) g_stat[i - NN] = 0u;
}

// ---- K1 (main stream): GEMM Wh = x @ Wn^T. 4 nodes/thread, 4 adjacent
//      cols/thread, XOR-swizzled smem W. ----
__global__ void __launch_bounds__(256) k_node(
    const float* __restrict__ x, const float* __restrict__ Wn,
    const float* __restrict__ att_s, const float* __restrict__ att_d) {
    __shared__ float4 Wt[64 * 32];   // 32 KB; unit u = col*32 + (f ^ ((col>>2)&7))
    int t = threadIdx.x;
    int tx = t & 15, ty = t >> 4;

    const float4* W4 = (const float4*)Wn;
#pragma unroll
    for (int i = 0; i < 8; i++) {
        int fidx = t + i * 256;          // 0..2047
        int col = fidx >> 5;
        int f = fidx & 31;
        Wt[col * 32 + (f ^ ((col >> 2) & 7))] = __ldg(W4 + fidx);
    }

    int nbase = blockIdx.x * 64 + ty * 4;
    const float4* xp[4];
    int node[4];
#pragma unroll
    for (int i = 0; i < 4; i++) {
        node[i] = nbase + i;
        int nc = (node[i] < NN) ? node[i] : (NN - 1);
        xp[i] = (const float4*)x + (size_t)nc * 32;
    }

    float4 acc[4];
#pragma unroll
    for (int i = 0; i < 4; i++) acc[i] = make_float4(0.f, 0.f, 0.f, 0.f);

    __syncthreads();

    int sw = tx & 7;
#pragma unroll 4
    for (int kk = 0; kk < 32; kk++) {
        float4 xv[4];
#pragma unroll
        for (int i = 0; i < 4; i++) xv[i] = __ldg(xp[i] + kk);
        float4 w0 = Wt[(4 * tx + 0) * 32 + (kk ^ sw)];
        float4 w1 = Wt[(4 * tx + 1) * 32 + (kk ^ sw)];
        float4 w2 = Wt[(4 * tx + 2) * 32 + (kk ^ sw)];
        float4 w3 = Wt[(4 * tx + 3) * 32 + (kk ^ sw)];
#pragma unroll
        for (int i = 0; i < 4; i++) {
            acc[i].x += dot4(xv[i], w0);
            acc[i].y += dot4(xv[i], w1);
            acc[i].z += dot4(xv[i], w2);
            acc[i].w += dot4(xv[i], w3);
        }
    }

    float4 as4 = __ldg((const float4*)att_s + tx);
    float4 ad4 = __ldg((const float4*)att_d + tx);
    int h = tx >> 2;
#pragma unroll
    for (int i = 0; i < 4; i++) {
        float ps = dot4(acc[i], as4);
        float pd = dot4(acc[i], ad4);
        ps += __shfl_xor_sync(0xffffffffu, ps, 1);
        pd += __shfl_xor_sync(0xffffffffu, pd, 1);
        ps += __shfl_xor_sync(0xffffffffu, ps, 2);
        pd += __shfl_xor_sync(0xffffffffu, pd, 2);
        if ((tx & 3) == 0 && node[i] < NN) {
            g_asrc[node[i] * 4 + h] = ps;
            g_adst[node[i] * 4 + h] = pd;
        }
    }

#pragma unroll
    for (int i = 0; i < 4; i++) {
        if (node[i] < NN)
            *(float4*)(g_Wh + (size_t)node[i] * OUTD + 4 * tx) = acc[i];
    }
}

// ---- K2 (side stream): degree histogram (REDG fast path) ----
__global__ void __launch_bounds__(256) k_count(const int* __restrict__ ei) {
    int i = blockIdx.x * 256 + threadIdx.x;
    if (i < EE) atomicAdd(&g_count[__ldg(ei + EE + i)], 1);
}

// ---- K3 (side stream): single-pass exclusive scan (aggregate lookback) ----
__global__ void __launch_bounds__(256) k_scan() {
    __shared__ int sh[256];
    __shared__ int prefix_sh;
    int b = blockIdx.x, t = threadIdx.x;
    int i = b * 256 + t;
    int c = (i < NN) ? g_count[i] : 0;
    sh[t] = c;
    __syncthreads();
#pragma unroll
    for (int o = 1; o < 256; o <<= 1) {
        int add = (t >= o) ? sh[t - o] : 0;
        __syncthreads();
        sh[t] += add;
        __syncthreads();
    }
    int incl = sh[t];
    if (t == 0) {
        unsigned total = (unsigned)sh[255];
        atomicExch(&g_stat[b], 0x80000000u | total);
    }
    if (t < 32) {
        int sum = 0;
        for (int idx = t; idx < b; idx += 32) {
            unsigned v;
            do { v = *(volatile unsigned*)&g_stat[idx]; } while (!(v & 0x80000000u));
            sum += (int)(v & 0x7fffffffu);
        }
#pragma unroll
        for (int o = 16; o >= 1; o >>= 1) sum += __shfl_xor_sync(0xffffffffu, sum, o);
        if (t == 0) prefix_sh = sum;
    }
    __syncthreads();
    if (i < NN) {
        int start = prefix_sh + incl - c;
        g_rowstart[i] = start;
        g_cursor[i] = start;
    }
}

// ---- K4 (joined): fused logits + exp + CSR bucket-scatter ----
__global__ void __launch_bounds__(256) k_edge_fused(
    const int* __restrict__ ei, const float* __restrict__ ea,
    const float* __restrict__ We) {
    __shared__ float4 we4[16];       // we4[h*4+j] = We[h][4j..4j+3]
    int t = threadIdx.x;
    if (t < 16) we4[t] = __ldg((const float4*)We + t);
    __syncthreads();
    int i = blockIdx.x * 256 + t;
    if (i >= EE) return;
    int s = ei[i];
    int d = ei[EE + i];
    float4 eav[4];
    const float4* er = (const float4*)(ea + (size_t)i * 16);
#pragma unroll
    for (int j = 0; j < 4; j++) eav[j] = __ldg(er + j);
    float4 as = *(const float4*)(g_asrc + (size_t)s * 4);
    float4 ad = *(const float4*)(g_adst + (size_t)d * 4);
    float base[4] = {as.x + ad.x, as.y + ad.y, as.z + ad.z, as.w + ad.w};
    float4 ex;
    float* exp_ = (float*)&ex;
#pragma unroll
    for (int h = 0; h < 4; h++) {
        float dot = 0.f;
#pragma unroll
        for (int j = 0; j < 4; j++) dot += dot4(eav[j], we4[h * 4 + j]);
        float v = base[h] + dot;
        v = (v > 0.f) ? v : 0.2f * v;      // leaky_relu
        exp_[h] = __expf(v);                // no max shift (~1e-7 relative effect)
    }
    int pos = atomicAdd(&g_cursor[d], 1);
    g_csr_src[pos] = s;
    *(float4*)(g_csr_ex + (size_t)pos * 4) = ex;
}

// ---- K5: warp-per-node aggregate, LDS-staged, 4x-unrolled gathers ----
__global__ void __launch_bounds__(256) k_agg(float* __restrict__ out,
                                             const float* __restrict__ bias) {
    __shared__ int   sh_src[8][32];
    __shared__ float sh_ex[8][128];
    int w = threadIdx.x >> 5;
    int lane = threadIdx.x & 31;
    int n = blockIdx.x * 8 + w;
    if (n >= NN) return;
    int cnt = __ldg(g_count + n);
    int start = __ldg(g_rowstart + n);
    int h = lane >> 3;
    float acc0 = 0.f, acc1 = 0.f;
    float dp0 = 0.f, dp1 = 0.f, dp2 = 0.f, dp3 = 0.f;

    for (int j0 = 0; j0 < cnt; j0 += 32) {
        int m = min(32, cnt - j0);
        if (lane < m) {
            int idx = start + j0 + lane;
            int s = __ldg(g_csr_src + idx);
            float4 ex = *(const float4*)(g_csr_ex + (size_t)idx * 4);
            sh_src[w][lane] = s;
            *(float4*)&sh_ex[w][lane * 4] = ex;
            dp0 += ex.x; dp1 += ex.y; dp2 += ex.z; dp3 += ex.w;
        }
        __syncwarp();
        int j = 0;
        for (; j + 4 <= m; j += 4) {
            int s0 = sh_src[w][j + 0], s1 = sh_src[w][j + 1];
            int s2 = sh_src[w][j + 2], s3 = sh_src[w][j + 3];
            float a0 = sh_ex[w][(j + 0) * 4 + h];
            float a1 = sh_ex[w][(j + 1) * 4 + h];
            float a2 = sh_ex[w][(j + 2) * 4 + h];
            float a3 = sh_ex[w][(j + 3) * 4 + h];
            float2 w0 = *(const float2*)(g_Wh + (size_t)s0 * OUTD + lane * 2);
            float2 w1 = *(const float2*)(g_Wh + (size_t)s1 * OUTD + lane * 2);
            float2 w2 = *(const float2*)(g_Wh + (size_t)s2 * OUTD + lane * 2);
            float2 w3 = *(const float2*)(g_Wh + (size_t)s3 * OUTD + lane * 2);
            acc0 += a0 * w0.x + a1 * w1.x + a2 * w2.x + a3 * w3.x;
            acc1 += a0 * w0.y + a1 * w1.y + a2 * w2.y + a3 * w3.y;
        }
        for (; j < m; j++) {
            int s = sh_src[w][j];
            float a = sh_ex[w][j * 4 + h];
            float2 wv = *(const float2*)(g_Wh + (size_t)s * OUTD + lane * 2);
            acc0 += a * wv.x;
            acc1 += a * wv.y;
        }
        __syncwarp();
    }
#pragma unroll
    for (int o = 16; o >= 1; o >>= 1) {
        dp0 += __shfl_xor_sync(0xffffffffu, dp0, o);
        dp1 += __shfl_xor_sync(0xffffffffu, dp1, o);
        dp2 += __shfl_xor_sync(0xffffffffu, dp2, o);
        dp3 += __shfl_xor_sync(0xffffffffu, dp3, o);
    }
    float den = (h == 0) ? dp0 : (h == 1) ? dp1 : (h == 2) ? dp2 : dp3;
    float inv = 1.f / (den + 1e-9f);
    int c0 = lane * 2;
    float v0 = acc0 * inv + __ldg(bias + c0);
    float v1 = acc1 * inv + __ldg(bias + c0 + 1);
    float2 r;
    r.x = (v0 > 0.f) ? v0 : expm1f(v0);
    r.y = (v1 > 0.f) ? v1 : expm1f(v1);
    *(float2*)(out + (size_t)n * OUTD + c0) = r;
}

extern "C" void kernel_launch(void* const* d_in, const int* in_sizes, int n_in,
                              void* d_out, int out_size) {
    const float* x     = (const float*)d_in[0];
    const int*   ei    = (const int*)d_in[1];
    const float* ea    = (const float*)d_in[2];
    const float* Wn    = (const float*)d_in[3];
    const float* We    = (const float*)d_in[4];
    const float* att_s = (const float*)d_in[5];
    const float* att_d = (const float*)d_in[6];
    const float* bias  = (const float*)d_in[7];
    float* out = (float*)d_out;

    // one-time host-side stream/event setup (no device memory involvement;
    // identical launch structure every call -> deterministic capture)
    static cudaStream_t s2 = 0;
    static cudaEvent_t evFork = 0, evJoin = 0;
    if (s2 == 0) {
        cudaStreamCreateWithFlags(&s2, cudaStreamNonBlocking);
        cudaEventCreateWithFlags(&evFork, cudaEventDisableTiming);
        cudaEventCreateWithFlags(&evJoin, cudaEventDisableTiming);
    }

    int ebl = (EE + 255) / 256;

    // fork: side stream does init -> count -> scan while main does the GEMM
    cudaEventRecord(evFork, 0);
    cudaStreamWaitEvent(s2, evFork, 0);
    k_init<<<(NN + NBLK + 255) / 256, 256, 0, s2>>>();
    k_count<<<ebl, 256, 0, s2>>>(ei);
    k_scan<<<NBLK, 256, 0, s2>>>();
    cudaEventRecord(evJoin, s2);

    k_node<<<(NN + 63) / 64, 256>>>(x, Wn, att_s, att_d);   // main stream

    // join: edge kernel needs both GEMM outputs and scan results
    cudaStreamWaitEvent(0, evJoin, 0);
    k_edge_fused<<<ebl, 256>>>(ei, ea, We);
    k_agg<<<(NN + 7) / 8, 256>>>(out, bias);
}